// round 16
// baseline (speedup 1.0000x reference)
#include <cuda_runtime.h>
#include <cuda_bf16.h>
#include <cuda_fp16.h>
#include <cstdint>

#define NNODES 100000
#define EMAX   1600000
#define DIM    128

// Scratch (__device__ globals: allocation-free rule)
__device__ __half g_hA[(size_t)NNODES * DIM];  // GEMM output buffer A
__device__ __half g_hB[(size_t)NNODES * DIM];  // GEMM output buffer B (double buffer)
__device__ __half g_a[(size_t)NNODES * DIM];   // activation plane (fp16, GEMM input)
__device__ float g_dinv[NNODES];
__device__ int   g_deg[NNODES];
__device__ int   g_cnt[NNODES];
__device__ int   g_rowptr[NNODES + 1];
__device__ int   g_bsum[256];
__device__ int   g_csr_src[EMAX];
// B-fragment table: [layer][half][ks][j][lane] -> uint2 (b0,b1 regs of mma B frag), fp16
#define TBL_PER_LAYER (2 * 8 * 8 * 32)
__device__ uint2 g_bfrag[3 * TBL_PER_LAYER];

// ================= helpers =================
__device__ __forceinline__ uint32_t smem_u32(const void* p) {
    uint32_t a;
    asm("{ .reg .u64 t; cvta.to.shared.u64 t, %1; cvt.u32.u64 %0, t; }" : "=r"(a) : "l"(p));
    return a;
}
__device__ __forceinline__ void ldm_x4(uint32_t* r, uint32_t addr) {
    asm volatile("ldmatrix.sync.aligned.m8n8.x4.shared.b16 {%0,%1,%2,%3}, [%4];"
                 : "=r"(r[0]), "=r"(r[1]), "=r"(r[2]), "=r"(r[3]) : "r"(addr));
}
__device__ __forceinline__ void mma_f16(float* c, const uint32_t* a, const uint32_t* b) {
    asm volatile(
        "mma.sync.aligned.m16n8k16.row.col.f32.f16.f16.f32 "
        "{%0,%1,%2,%3}, {%4,%5,%6,%7}, {%8,%9}, {%0,%1,%2,%3};"
        : "+f"(c[0]), "+f"(c[1]), "+f"(c[2]), "+f"(c[3])
        : "r"(a[0]), "r"(a[1]), "r"(a[2]), "r"(a[3]), "r"(b[0]), "r"(b[1]));
}
__device__ __forceinline__ void cp_async16(uint32_t saddr, const void* gptr) {
    asm volatile("cp.async.cg.shared.global [%0], [%1], 16;"
                 :: "r"(saddr), "l"(gptr) : "memory");
}
__device__ __forceinline__ void cp_async_wait_all() {
    asm volatile("cp.async.commit_group;" ::: "memory");
    asm volatile("cp.async.wait_group 0;" ::: "memory");
}

// ================= prep: W frag table (fp16) + x -> fp16 plane =================
__global__ void prep_kernel(const float* __restrict__ W1, const float* __restrict__ W2,
                            const float* __restrict__ W3,
                            uint2* __restrict__ tbl,
                            const float* __restrict__ x, __half* __restrict__ xa, int n) {
    int i = blockIdx.x * blockDim.x + threadIdx.x;
    if (i < 3 * TBL_PER_LAYER) {
        int lane = i & 31;
        int j    = (i >> 5) & 7;
        int ks   = (i >> 8) & 7;
        int half = (i >> 11) & 1;
        int l    = i >> 12;
        const float* W = (l == 0) ? W1 : (l == 1) ? W2 : W3;
        int nn = half * 64 + j * 8 + (lane >> 2);
        int k  = ks * 16 + (lane & 3) * 2;
        __half2 b0 = __halves2half2(__float2half_rn(W[(size_t)k * DIM + nn]),
                                    __float2half_rn(W[(size_t)(k + 1) * DIM + nn]));
        __half2 b1 = __halves2half2(__float2half_rn(W[(size_t)(k + 8) * DIM + nn]),
                                    __float2half_rn(W[(size_t)(k + 9) * DIM + nn]));
        tbl[i] = make_uint2(*(uint32_t*)&b0, *(uint32_t*)&b1);
    }
    // x -> fp16 plane, float2 granules
    long tot = (long)n * 64;
    for (long j = i; j < tot; j += (long)gridDim.x * blockDim.x) {
        float2 v = *(const float2*)(x + j * 2);
        __half2 p = __float22half2_rn(v);
        *(uint32_t*)(xa + j * 2) = *(uint32_t*)&p;
    }
}

// ================= CSR build =================
__global__ void zero2_kernel(int* __restrict__ a, int* __restrict__ b, int n) {
    int i = blockIdx.x * blockDim.x + threadIdx.x;
    if (i < n) { a[i] = 0; b[i] = 0; }
}
__global__ void deg_acc_kernel(const int* __restrict__ dst, int* __restrict__ deg, int E) {
    int e = blockIdx.x * blockDim.x + threadIdx.x;
    if (e < E) atomicAdd(&deg[dst[e]], 1);
}
// scan1 also emits dinv = rsqrt(deg+1); per-1024-chunk exclusive scan + chunk sums
__global__ void scan1_kernel(const int* __restrict__ in, int* __restrict__ out,
                             int* __restrict__ bsum, float* __restrict__ dinv, int n) {
    __shared__ int sh[256];
    int t = threadIdx.x;
    int i0 = blockIdx.x * 1024 + t * 4;
    int v[4];
#pragma unroll
    for (int k = 0; k < 4; k++) {
        v[k] = (i0 + k < n) ? in[i0 + k] : 0;
        if (i0 + k < n) dinv[i0 + k] = rsqrtf((float)(v[k] + 1));
    }
    int s = v[0] + v[1] + v[2] + v[3];
    sh[t] = s;
    __syncthreads();
#pragma unroll
    for (int off = 1; off < 256; off <<= 1) {
        int x = (t >= off) ? sh[t - off] : 0;
        __syncthreads();
        sh[t] += x;
        __syncthreads();
    }
    int run = sh[t] - s;
#pragma unroll
    for (int k = 0; k < 4; k++) {
        if (i0 + k < n) out[i0 + k] = run;
        run += v[k];
    }
    if (t == 255) bsum[blockIdx.x] = sh[255];
}
// scan3: adds exclusive prefix of bsum (computed in-block) — scan2 folded in.
__global__ void scan3_kernel(int* __restrict__ rowptr, const int* __restrict__ bsum,
                             int n, int E) {
    __shared__ int red[256];
    int i = blockIdx.x * blockDim.x + threadIdx.x;
    int c = (blockIdx.x * blockDim.x) >> 10;   // same chunk for whole block
    int t = threadIdx.x;
    int s = 0;
    for (int q = t; q < c; q += blockDim.x) s += bsum[q];
    red[t] = s;
    __syncthreads();
    for (int off = 128; off > 0; off >>= 1) {
        if (t < off) red[t] += red[t + off];
        __syncthreads();
    }
    int pre = red[0];
    if (i < n) rowptr[i] += pre;
    if (blockIdx.x == 0 && t == 0) rowptr[n] = E;
}
__global__ void fill_kernel(const int* __restrict__ src, const int* __restrict__ dst,
                            const int* __restrict__ rowptr, int* __restrict__ cnt,
                            int* __restrict__ csr_src, int E) {
    int e = blockIdx.x * blockDim.x + threadIdx.x;
    if (e >= E) return;
    int s = src[e], d = dst[e];
    int pos = rowptr[d] + atomicAdd(&cnt[d], 1);
    csr_src[pos] = s;
}

// ================= HMMA GEMM: C[M,128] = A[M,128] @ W, fp16 in/out =================
// TILE_M=64, 128 threads (4 warps, warp tile 32x64), 4 CTAs/SM for phase overlap.
#define TILE_M 64
#define NTHR   128
#define LDA 136           // fp16 elems per smem row (pad 8: conflict-free ldmatrix)
#define LDAB (LDA * 2)    // 272 bytes per smem row
#define SM_TOT (TILE_M * LDAB)   // 17408

__global__ __launch_bounds__(NTHR, 4)
void mma_gemm(const __half* __restrict__ A,
              const uint2* __restrict__ Tbl,
              __half* __restrict__ C, int M) {
    extern __shared__ char smem[];
    const uint32_t sb = smem_u32(smem);
    const int tid  = threadIdx.x;
    const int wid  = tid >> 5;
    const int lane = tid & 31;
    const int row0 = blockIdx.x * TILE_M;

    // ---- async copy A plane into padded smem (16B chunks) ----
    {
        const char* ga = (const char*)(A + (size_t)row0 * DIM);
        for (int i = tid; i < TILE_M * 16; i += NTHR) {
            int row = i >> 4, c = (i & 15) * 16;
            if (row0 + row < M)
                cp_async16(sb + (uint32_t)(row * LDAB + c), ga + row * 256 + c);
        }
        cp_async_wait_all();
    }
    __syncthreads();

    const int wr   = (wid >> 1) * 32;
    const int half = wid & 1;
    const int wc   = half * 64;

    float acc[2][8][4];
#pragma unroll
    for (int rt = 0; rt < 2; rt++)
#pragma unroll
        for (int j = 0; j < 8; j++)
#pragma unroll
            for (int q = 0; q < 4; q++) acc[rt][j][q] = 0.f;

    const int m  = lane >> 3;
    const int rr = lane & 7;

#pragma unroll
    for (int ks = 0; ks < 8; ks++) {
        const int k0 = ks * 16;

        uint32_t ah[2][4];
#pragma unroll
        for (int rt = 0; rt < 2; rt++) {
            int arow = wr + rt * 16 + ((m & 1) ? 8 : 0) + rr;
            int acol = k0 + ((m >> 1) ? 8 : 0);
            ldm_x4(ah[rt], sb + (uint32_t)(arow * LDA + acol) * 2);
        }

        const uint2* pb = Tbl + ((size_t)(half * 8 + ks) * 8) * 32 + lane;
        uint32_t bf[8][2];
#pragma unroll
        for (int j = 0; j < 8; j++) {
            uint2 v = __ldg(pb + j * 32);
            bf[j][0] = v.x; bf[j][1] = v.y;
        }
#pragma unroll
        for (int rt = 0; rt < 2; rt++)
#pragma unroll
            for (int j = 0; j < 8; j++)
                mma_f16(acc[rt][j], ah[rt], bf[j]);
    }

    // ---- epilogue: fragments -> fp16 staging smem -> coalesced global ----
    __syncthreads();
    __half* stage = (__half*)smem;
    const int g  = lane >> 2;
    const int cq = (lane & 3) * 2;
#pragma unroll
    for (int rt = 0; rt < 2; rt++)
#pragma unroll
        for (int j = 0; j < 8; j++) {
            int row = wr + rt * 16 + g;
            int col = wc + j * 8 + cq;
            *(__half2*)(stage + row * LDA + col) =
                __float22half2_rn(make_float2(acc[rt][j][0], acc[rt][j][1]));
            *(__half2*)(stage + (row + 8) * LDA + col) =
                __float22half2_rn(make_float2(acc[rt][j][2], acc[rt][j][3]));
        }
    __syncthreads();

    for (int i = tid; i < TILE_M * 16; i += NTHR) {
        int r = i >> 4, cp = i & 15;
        if (row0 + r < M) {
            uint4 v = *(uint4*)(stage + r * LDA + cp * 8);
            *(uint4*)(C + (size_t)(row0 + r) * DIM + cp * 8) = v;
        }
    }
}

// ================= fused gather (fp16 h, fp32 accumulate) =================
__device__ __forceinline__ float4 h4_to_f4(uint2 u) {
    float2 f0 = __half22float2(*(__half2*)&u.x);
    float2 f1 = __half22float2(*(__half2*)&u.y);
    return make_float4(f0.x, f0.y, f1.x, f1.y);
}

template <bool RELU, bool F16OUT>
__global__ __launch_bounds__(256)
void gather_kernel(const __half* __restrict__ h, const float* __restrict__ bias,
                   const int* __restrict__ rowptr, const int* __restrict__ csr_src,
                   const float* __restrict__ dinv,
                   float* __restrict__ outf, __half* __restrict__ oa,
                   int base, int m) {
    int warp = (blockIdx.x * blockDim.x + threadIdx.x) >> 5;
    int lane = threadIdx.x & 31;
    if (warp >= m) return;
    const int d = base + warp;
    const int c4 = lane * 4;

    float di = __ldg(&dinv[d]);
    float s  = di * di;
    float4 self = h4_to_f4(*(const uint2*)(h + (size_t)d * DIM + c4));
    float4 bb   = *(const float4*)(bias + c4);
    float4 acc;
    acc.x = fmaf(self.x, s, bb.x);
    acc.y = fmaf(self.y, s, bb.y);
    acc.z = fmaf(self.z, s, bb.z);
    acc.w = fmaf(self.w, s, bb.w);

    int j   = __ldg(&rowptr[d]);
    int end = __ldg(&rowptr[d + 1]);

    for (; j + 3 < end; j += 4) {
        int   s0 = __ldg(&csr_src[j]);
        int   s1 = __ldg(&csr_src[j + 1]);
        int   s2 = __ldg(&csr_src[j + 2]);
        int   s3 = __ldg(&csr_src[j + 3]);
        float c0 = __ldg(&dinv[s0]) * di;
        float c1 = __ldg(&dinv[s1]) * di;
        float c2 = __ldg(&dinv[s2]) * di;
        float c3 = __ldg(&dinv[s3]) * di;
        uint2 u0 = *(const uint2*)(h + (size_t)s0 * DIM + c4);
        uint2 u1 = *(const uint2*)(h + (size_t)s1 * DIM + c4);
        uint2 u2 = *(const uint2*)(h + (size_t)s2 * DIM + c4);
        uint2 u3 = *(const uint2*)(h + (size_t)s3 * DIM + c4);
        float4 v0 = h4_to_f4(u0);
        float4 v1 = h4_to_f4(u1);
        float4 v2 = h4_to_f4(u2);
        float4 v3 = h4_to_f4(u3);
        acc.x = fmaf(v0.x, c0, acc.x);
        acc.y = fmaf(v0.y, c0, acc.y);
        acc.z = fmaf(v0.z, c0, acc.z);
        acc.w = fmaf(v0.w, c0, acc.w);
        acc.x = fmaf(v1.x, c1, acc.x);
        acc.y = fmaf(v1.y, c1, acc.y);
        acc.z = fmaf(v1.z, c1, acc.z);
        acc.w = fmaf(v1.w, c1, acc.w);
        acc.x = fmaf(v2.x, c2, acc.x);
        acc.y = fmaf(v2.y, c2, acc.y);
        acc.z = fmaf(v2.z, c2, acc.z);
        acc.w = fmaf(v2.w, c2, acc.w);
        acc.x = fmaf(v3.x, c3, acc.x);
        acc.y = fmaf(v3.y, c3, acc.y);
        acc.z = fmaf(v3.z, c3, acc.z);
        acc.w = fmaf(v3.w, c3, acc.w);
    }
    for (; j < end; j++) {
        int   s0 = __ldg(&csr_src[j]);
        float c0 = __ldg(&dinv[s0]) * di;
        float4 v0 = h4_to_f4(*(const uint2*)(h + (size_t)s0 * DIM + c4));
        acc.x = fmaf(v0.x, c0, acc.x);
        acc.y = fmaf(v0.y, c0, acc.y);
        acc.z = fmaf(v0.z, c0, acc.z);
        acc.w = fmaf(v0.w, c0, acc.w);
    }

    if (RELU) {
        acc.x = fmaxf(acc.x, 0.f);
        acc.y = fmaxf(acc.y, 0.f);
        acc.z = fmaxf(acc.z, 0.f);
        acc.w = fmaxf(acc.w, 0.f);
    }

    if (F16OUT) {
        __half2 p0 = __float22half2_rn(make_float2(acc.x, acc.y));
        __half2 p1 = __float22half2_rn(make_float2(acc.z, acc.w));
        *(uint2*)(oa + (size_t)d * DIM + c4) = make_uint2(*(uint32_t*)&p0, *(uint32_t*)&p1);
    } else {
        *(float4*)(outf + (size_t)d * DIM + c4) = acc;
    }
}

extern "C" void kernel_launch(void* const* d_in, const int* in_sizes, int n_in,
                              void* d_out, int out_size) {
    const float* x  = (const float*)d_in[0];
    const int*   ei = (const int*)d_in[1];
    const float* W1 = (const float*)d_in[2];
    const float* b1 = (const float*)d_in[3];
    const float* W2 = (const float*)d_in[4];
    const float* b2 = (const float*)d_in[5];
    const float* W3 = (const float*)d_in[6];
    const float* b3 = (const float*)d_in[7];
    float*       out = (float*)d_out;

    const int N = in_sizes[0] / DIM;
    const int E = in_sizes[1] / 2;
    const int* src = ei;
    const int* dst = ei + E;

    __half *hA, *hB, *a;
    float* dinv;
    int *deg, *cnt, *rowptr, *bsum, *csr_src;
    uint2* tbl;
    cudaGetSymbolAddress((void**)&hA,      g_hA);
    cudaGetSymbolAddress((void**)&hB,      g_hB);
    cudaGetSymbolAddress((void**)&a,       g_a);
    cudaGetSymbolAddress((void**)&dinv,    g_dinv);
    cudaGetSymbolAddress((void**)&deg,     g_deg);
    cudaGetSymbolAddress((void**)&cnt,     g_cnt);
    cudaGetSymbolAddress((void**)&rowptr,  g_rowptr);
    cudaGetSymbolAddress((void**)&bsum,    g_bsum);
    cudaGetSymbolAddress((void**)&csr_src, g_csr_src);
    cudaGetSymbolAddress((void**)&tbl,     g_bfrag);

    // One-time: side stream + events (no device memory involved)
    static cudaStream_t sB = nullptr;
    static cudaEvent_t evFork = nullptr, evJoin0 = nullptr;
    static cudaEvent_t evG[8], evJ1 = nullptr, evJ2 = nullptr;
    if (!sB) {
        cudaStreamCreateWithFlags(&sB, cudaStreamNonBlocking);
        cudaEventCreateWithFlags(&evFork,  cudaEventDisableTiming);
        cudaEventCreateWithFlags(&evJoin0, cudaEventDisableTiming);
        for (int k = 0; k < 8; k++) cudaEventCreateWithFlags(&evG[k], cudaEventDisableTiming);
        cudaEventCreateWithFlags(&evJ1, cudaEventDisableTiming);
        cudaEventCreateWithFlags(&evJ2, cudaEventDisableTiming);
        cudaFuncSetAttribute(mma_gemm, cudaFuncAttributeMaxDynamicSharedMemorySize, SM_TOT);
    }

    const int TB = 256;
    const int n_blk  = (N + TB - 1) / TB;
    const int e_blk  = (E + TB - 1) / TB;
    const int gemm_g = (N + TILE_M - 1) / TILE_M;
    const int nch    = (N + 1023) / 1024;

    const int CHUNK   = 25024;                 // multiple of 64
    const int nchunks = (N + CHUNK - 1) / CHUNK;

    // ---- fork: CSR build on side stream, prep+GEMM1 on main stream ----
    cudaEventRecord(evFork, 0);
    cudaStreamWaitEvent(sB, evFork, 0);

    zero2_kernel<<<n_blk, TB, 0, sB>>>(deg, cnt, N);
    deg_acc_kernel<<<e_blk, TB, 0, sB>>>(dst, deg, E);
    scan1_kernel<<<nch, 256, 0, sB>>>(deg, rowptr, bsum, dinv, N);
    scan3_kernel<<<n_blk, TB, 0, sB>>>(rowptr, bsum, N, E);
    fill_kernel<<<e_blk, TB, 0, sB>>>(src, dst, rowptr, cnt, csr_src, E);
    cudaEventRecord(evJoin0, sB);

    prep_kernel<<<8192, TB>>>(W1, W2, W3, tbl, x, a, N);
    mma_gemm<<<gemm_g, NTHR, SM_TOT>>>(a, tbl, hA, N);     // layer-1 GEMM -> hA

    cudaStreamWaitEvent(0, evJoin0, 0);

    // ---- pipelined: gather1 (reads hA, writes a) || gemm2 chunks (reads a, writes hB) ----
    for (int k = 0; k < nchunks; k++) {
        int off = k * CHUNK;
        int m   = (N - off < CHUNK) ? (N - off) : CHUNK;
        gather_kernel<true, true><<<(m * 32 + TB - 1) / TB, TB>>>(
            hA, b1, rowptr, csr_src, dinv, nullptr, a, off, m);
        cudaEventRecord(evG[k], 0);
        cudaStreamWaitEvent(sB, evG[k], 0);
        mma_gemm<<<(m + TILE_M - 1) / TILE_M, NTHR, SM_TOT, sB>>>(
            a + (size_t)off * DIM, tbl + TBL_PER_LAYER, hB + (size_t)off * DIM, m);
    }
    cudaEventRecord(evJ1, sB);
    cudaStreamWaitEvent(0, evJ1, 0);

    // ---- pipelined: gather2 (reads hB, writes a) || gemm3 chunks (reads a, writes hA) ----
    for (int k = 0; k < nchunks; k++) {
        int off = k * CHUNK;
        int m   = (N - off < CHUNK) ? (N - off) : CHUNK;
        gather_kernel<true, true><<<(m * 32 + TB - 1) / TB, TB>>>(
            hB, b2, rowptr, csr_src, dinv, nullptr, a, off, m);
        cudaEventRecord(evG[4 + k], 0);
        cudaStreamWaitEvent(sB, evG[4 + k], 0);
        mma_gemm<<<(m + TILE_M - 1) / TILE_M, NTHR, SM_TOT, sB>>>(
            a + (size_t)off * DIM, tbl + 2 * TBL_PER_LAYER, hA + (size_t)off * DIM, m);
    }
    cudaEventRecord(evJ2, sB);
    cudaStreamWaitEvent(0, evJ2, 0);

    // ---- final gather (reads hA) -> d_out (fp32) ----
    gather_kernel<false, false><<<(N * 32 + TB - 1) / TB, TB>>>(
        hA, b3, rowptr, csr_src, dinv, out, nullptr, 0, N);
}

// round 17
// speedup vs baseline: 1.1474x; 1.1474x over previous
#include <cuda_runtime.h>
#include <cuda_bf16.h>
#include <cuda_fp16.h>
#include <cstdint>

#define NNODES 100000
#define EMAX   1600000
#define DIM    128

// Scratch (__device__ globals: allocation-free rule)
__device__ __half g_h[(size_t)NNODES * DIM];   // GEMM output (fp16, gather input)
__device__ __half g_a[(size_t)NNODES * DIM];   // activation plane (fp16, GEMM input)
__device__ float g_dinv[NNODES];
__device__ int   g_deg[NNODES];
__device__ int   g_cnt[NNODES];
__device__ int   g_rowptr[NNODES + 1];
__device__ int   g_bsum[256];
__device__ int   g_csr_src[EMAX];
// B-fragment table: [layer][half][ks][j][lane] -> uint2 (b0,b1 regs of mma B frag), fp16
#define TBL_PER_LAYER (2 * 8 * 8 * 32)
__device__ uint2 g_bfrag[3 * TBL_PER_LAYER];

// ================= helpers =================
__device__ __forceinline__ uint32_t smem_u32(const void* p) {
    uint32_t a;
    asm("{ .reg .u64 t; cvta.to.shared.u64 t, %1; cvt.u32.u64 %0, t; }" : "=r"(a) : "l"(p));
    return a;
}
__device__ __forceinline__ void ldm_x4(uint32_t* r, uint32_t addr) {
    asm volatile("ldmatrix.sync.aligned.m8n8.x4.shared.b16 {%0,%1,%2,%3}, [%4];"
                 : "=r"(r[0]), "=r"(r[1]), "=r"(r[2]), "=r"(r[3]) : "r"(addr));
}
__device__ __forceinline__ void mma_f16(float* c, const uint32_t* a, const uint32_t* b) {
    asm volatile(
        "mma.sync.aligned.m16n8k16.row.col.f32.f16.f16.f32 "
        "{%0,%1,%2,%3}, {%4,%5,%6,%7}, {%8,%9}, {%0,%1,%2,%3};"
        : "+f"(c[0]), "+f"(c[1]), "+f"(c[2]), "+f"(c[3])
        : "r"(a[0]), "r"(a[1]), "r"(a[2]), "r"(a[3]), "r"(b[0]), "r"(b[1]));
}
__device__ __forceinline__ void cp_async16(uint32_t saddr, const void* gptr) {
    asm volatile("cp.async.cg.shared.global [%0], [%1], 16;"
                 :: "r"(saddr), "l"(gptr) : "memory");
}
__device__ __forceinline__ void cp_async_wait_all() {
    asm volatile("cp.async.commit_group;" ::: "memory");
    asm volatile("cp.async.wait_group 0;" ::: "memory");
}

// ================= prep: W frag table (fp16) + x -> fp16 plane =================
__global__ void prep_kernel(const float* __restrict__ W1, const float* __restrict__ W2,
                            const float* __restrict__ W3,
                            uint2* __restrict__ tbl,
                            const float* __restrict__ x, __half* __restrict__ xa, int n) {
    int i = blockIdx.x * blockDim.x + threadIdx.x;
    if (i < 3 * TBL_PER_LAYER) {
        int lane = i & 31;
        int j    = (i >> 5) & 7;
        int ks   = (i >> 8) & 7;
        int half = (i >> 11) & 1;
        int l    = i >> 12;
        const float* W = (l == 0) ? W1 : (l == 1) ? W2 : W3;
        int nn = half * 64 + j * 8 + (lane >> 2);
        int k  = ks * 16 + (lane & 3) * 2;
        __half2 b0 = __halves2half2(__float2half_rn(W[(size_t)k * DIM + nn]),
                                    __float2half_rn(W[(size_t)(k + 1) * DIM + nn]));
        __half2 b1 = __halves2half2(__float2half_rn(W[(size_t)(k + 8) * DIM + nn]),
                                    __float2half_rn(W[(size_t)(k + 9) * DIM + nn]));
        tbl[i] = make_uint2(*(uint32_t*)&b0, *(uint32_t*)&b1);
    }
    // x -> fp16 plane, float2 granules
    long tot = (long)n * 64;
    for (long j = i; j < tot; j += (long)gridDim.x * blockDim.x) {
        float2 v = *(const float2*)(x + j * 2);
        __half2 p = __float22half2_rn(v);
        *(uint32_t*)(xa + j * 2) = *(uint32_t*)&p;
    }
}

// ================= CSR build =================
__global__ void zero2_kernel(int* __restrict__ a, int* __restrict__ b, int n) {
    int i = blockIdx.x * blockDim.x + threadIdx.x;
    if (i < n) { a[i] = 0; b[i] = 0; }
}
__global__ void deg_acc_kernel(const int* __restrict__ dst, int* __restrict__ deg, int E) {
    int e = blockIdx.x * blockDim.x + threadIdx.x;
    if (e < E) atomicAdd(&deg[dst[e]], 1);
}
// scan1 also emits dinv = rsqrt(deg+1); per-1024-chunk exclusive scan + chunk sums
__global__ void scan1_kernel(const int* __restrict__ in, int* __restrict__ out,
                             int* __restrict__ bsum, float* __restrict__ dinv, int n) {
    __shared__ int sh[256];
    int t = threadIdx.x;
    int i0 = blockIdx.x * 1024 + t * 4;
    int v[4];
#pragma unroll
    for (int k = 0; k < 4; k++) {
        v[k] = (i0 + k < n) ? in[i0 + k] : 0;
        if (i0 + k < n) dinv[i0 + k] = rsqrtf((float)(v[k] + 1));
    }
    int s = v[0] + v[1] + v[2] + v[3];
    sh[t] = s;
    __syncthreads();
#pragma unroll
    for (int off = 1; off < 256; off <<= 1) {
        int x = (t >= off) ? sh[t - off] : 0;
        __syncthreads();
        sh[t] += x;
        __syncthreads();
    }
    int run = sh[t] - s;
#pragma unroll
    for (int k = 0; k < 4; k++) {
        if (i0 + k < n) out[i0 + k] = run;
        run += v[k];
    }
    if (t == 255) bsum[blockIdx.x] = sh[255];
}
// scan3: adds exclusive prefix of bsum (computed in-block) — scan2 folded in.
__global__ void scan3_kernel(int* __restrict__ rowptr, const int* __restrict__ bsum,
                             int n, int E) {
    __shared__ int red[256];
    int i = blockIdx.x * blockDim.x + threadIdx.x;
    int c = (blockIdx.x * blockDim.x) >> 10;   // same chunk for whole block
    int t = threadIdx.x;
    int s = 0;
    for (int q = t; q < c; q += blockDim.x) s += bsum[q];
    red[t] = s;
    __syncthreads();
    for (int off = 128; off > 0; off >>= 1) {
        if (t < off) red[t] += red[t + off];
        __syncthreads();
    }
    int pre = red[0];
    if (i < n) rowptr[i] += pre;
    if (blockIdx.x == 0 && t == 0) rowptr[n] = E;
}
__global__ void fill_kernel(const int* __restrict__ src, const int* __restrict__ dst,
                            const int* __restrict__ rowptr, int* __restrict__ cnt,
                            int* __restrict__ csr_src, int E) {
    int e = blockIdx.x * blockDim.x + threadIdx.x;
    if (e >= E) return;
    int s = src[e], d = dst[e];
    int pos = rowptr[d] + atomicAdd(&cnt[d], 1);
    csr_src[pos] = s;
}

// ================= HMMA GEMM: C[M,128] = A[M,128] @ W, fp16 in/out =================
// TILE_M=64, 128 threads (4 warps, warp tile 32x64), 4 CTAs/SM for phase overlap.
#define TILE_M 64
#define NTHR   128
#define LDA 136           // fp16 elems per smem row (pad 8: conflict-free ldmatrix)
#define LDAB (LDA * 2)    // 272 bytes per smem row
#define SM_TOT (TILE_M * LDAB)   // 17408

__global__ __launch_bounds__(NTHR, 4)
void mma_gemm(const __half* __restrict__ A,
              const uint2* __restrict__ Tbl,
              __half* __restrict__ C, int M) {
    extern __shared__ char smem[];
    const uint32_t sb = smem_u32(smem);
    const int tid  = threadIdx.x;
    const int wid  = tid >> 5;
    const int lane = tid & 31;
    const int row0 = blockIdx.x * TILE_M;

    // ---- async copy A plane into padded smem (16B chunks) ----
    {
        const char* ga = (const char*)(A + (size_t)row0 * DIM);
        for (int i = tid; i < TILE_M * 16; i += NTHR) {
            int row = i >> 4, c = (i & 15) * 16;
            if (row0 + row < M)
                cp_async16(sb + (uint32_t)(row * LDAB + c), ga + row * 256 + c);
        }
        cp_async_wait_all();
    }
    __syncthreads();

    const int wr   = (wid >> 1) * 32;
    const int half = wid & 1;
    const int wc   = half * 64;

    float acc[2][8][4];
#pragma unroll
    for (int rt = 0; rt < 2; rt++)
#pragma unroll
        for (int j = 0; j < 8; j++)
#pragma unroll
            for (int q = 0; q < 4; q++) acc[rt][j][q] = 0.f;

    const int m  = lane >> 3;
    const int rr = lane & 7;

#pragma unroll
    for (int ks = 0; ks < 8; ks++) {
        const int k0 = ks * 16;

        uint32_t ah[2][4];
#pragma unroll
        for (int rt = 0; rt < 2; rt++) {
            int arow = wr + rt * 16 + ((m & 1) ? 8 : 0) + rr;
            int acol = k0 + ((m >> 1) ? 8 : 0);
            ldm_x4(ah[rt], sb + (uint32_t)(arow * LDA + acol) * 2);
        }

        const uint2* pb = Tbl + ((size_t)(half * 8 + ks) * 8) * 32 + lane;
        uint32_t bf[8][2];
#pragma unroll
        for (int j = 0; j < 8; j++) {
            uint2 v = __ldg(pb + j * 32);
            bf[j][0] = v.x; bf[j][1] = v.y;
        }
#pragma unroll
        for (int rt = 0; rt < 2; rt++)
#pragma unroll
            for (int j = 0; j < 8; j++)
                mma_f16(acc[rt][j], ah[rt], bf[j]);
    }

    // ---- epilogue: fragments -> fp16 staging smem -> coalesced global ----
    __syncthreads();
    __half* stage = (__half*)smem;
    const int g  = lane >> 2;
    const int cq = (lane & 3) * 2;
#pragma unroll
    for (int rt = 0; rt < 2; rt++)
#pragma unroll
        for (int j = 0; j < 8; j++) {
            int row = wr + rt * 16 + g;
            int col = wc + j * 8 + cq;
            *(__half2*)(stage + row * LDA + col) =
                __float22half2_rn(make_float2(acc[rt][j][0], acc[rt][j][1]));
            *(__half2*)(stage + (row + 8) * LDA + col) =
                __float22half2_rn(make_float2(acc[rt][j][2], acc[rt][j][3]));
        }
    __syncthreads();

    for (int i = tid; i < TILE_M * 16; i += NTHR) {
        int r = i >> 4, cp = i & 15;
        if (row0 + r < M) {
            uint4 v = *(uint4*)(stage + r * LDA + cp * 8);
            *(uint4*)(C + (size_t)(row0 + r) * DIM + cp * 8) = v;
        }
    }
}

// ================= fused gather (fp16 h, fp32 accumulate) =================
__device__ __forceinline__ float4 h4_to_f4(uint2 u) {
    float2 f0 = __half22float2(*(__half2*)&u.x);
    float2 f1 = __half22float2(*(__half2*)&u.y);
    return make_float4(f0.x, f0.y, f1.x, f1.y);
}

template <bool RELU, bool F16OUT>
__global__ __launch_bounds__(256)
void gather_kernel(const __half* __restrict__ h, const float* __restrict__ bias,
                   const int* __restrict__ rowptr, const int* __restrict__ csr_src,
                   const float* __restrict__ dinv,
                   float* __restrict__ outf, __half* __restrict__ oa, int n) {
    int warp = (blockIdx.x * blockDim.x + threadIdx.x) >> 5;
    int lane = threadIdx.x & 31;
    if (warp >= n) return;
    const int d = warp;
    const int c4 = lane * 4;

    float di = __ldg(&dinv[d]);
    float s  = di * di;
    float4 self = h4_to_f4(*(const uint2*)(h + (size_t)d * DIM + c4));
    float4 bb   = *(const float4*)(bias + c4);
    float4 acc;
    acc.x = fmaf(self.x, s, bb.x);
    acc.y = fmaf(self.y, s, bb.y);
    acc.z = fmaf(self.z, s, bb.z);
    acc.w = fmaf(self.w, s, bb.w);

    int j   = __ldg(&rowptr[d]);
    int end = __ldg(&rowptr[d + 1]);

    for (; j + 3 < end; j += 4) {
        int   s0 = __ldg(&csr_src[j]);
        int   s1 = __ldg(&csr_src[j + 1]);
        int   s2 = __ldg(&csr_src[j + 2]);
        int   s3 = __ldg(&csr_src[j + 3]);
        float c0 = __ldg(&dinv[s0]) * di;
        float c1 = __ldg(&dinv[s1]) * di;
        float c2 = __ldg(&dinv[s2]) * di;
        float c3 = __ldg(&dinv[s3]) * di;
        uint2 u0 = *(const uint2*)(h + (size_t)s0 * DIM + c4);
        uint2 u1 = *(const uint2*)(h + (size_t)s1 * DIM + c4);
        uint2 u2 = *(const uint2*)(h + (size_t)s2 * DIM + c4);
        uint2 u3 = *(const uint2*)(h + (size_t)s3 * DIM + c4);
        float4 v0 = h4_to_f4(u0);
        float4 v1 = h4_to_f4(u1);
        float4 v2 = h4_to_f4(u2);
        float4 v3 = h4_to_f4(u3);
        acc.x = fmaf(v0.x, c0, acc.x);
        acc.y = fmaf(v0.y, c0, acc.y);
        acc.z = fmaf(v0.z, c0, acc.z);
        acc.w = fmaf(v0.w, c0, acc.w);
        acc.x = fmaf(v1.x, c1, acc.x);
        acc.y = fmaf(v1.y, c1, acc.y);
        acc.z = fmaf(v1.z, c1, acc.z);
        acc.w = fmaf(v1.w, c1, acc.w);
        acc.x = fmaf(v2.x, c2, acc.x);
        acc.y = fmaf(v2.y, c2, acc.y);
        acc.z = fmaf(v2.z, c2, acc.z);
        acc.w = fmaf(v2.w, c2, acc.w);
        acc.x = fmaf(v3.x, c3, acc.x);
        acc.y = fmaf(v3.y, c3, acc.y);
        acc.z = fmaf(v3.z, c3, acc.z);
        acc.w = fmaf(v3.w, c3, acc.w);
    }
    for (; j < end; j++) {
        int   s0 = __ldg(&csr_src[j]);
        float c0 = __ldg(&dinv[s0]) * di;
        float4 v0 = h4_to_f4(*(const uint2*)(h + (size_t)s0 * DIM + c4));
        acc.x = fmaf(v0.x, c0, acc.x);
        acc.y = fmaf(v0.y, c0, acc.y);
        acc.z = fmaf(v0.z, c0, acc.z);
        acc.w = fmaf(v0.w, c0, acc.w);
    }

    if (RELU) {
        acc.x = fmaxf(acc.x, 0.f);
        acc.y = fmaxf(acc.y, 0.f);
        acc.z = fmaxf(acc.z, 0.f);
        acc.w = fmaxf(acc.w, 0.f);
    }

    if (F16OUT) {
        __half2 p0 = __float22half2_rn(make_float2(acc.x, acc.y));
        __half2 p1 = __float22half2_rn(make_float2(acc.z, acc.w));
        *(uint2*)(oa + (size_t)d * DIM + c4) = make_uint2(*(uint32_t*)&p0, *(uint32_t*)&p1);
    } else {
        *(float4*)(outf + (size_t)d * DIM + c4) = acc;
    }
}

extern "C" void kernel_launch(void* const* d_in, const int* in_sizes, int n_in,
                              void* d_out, int out_size) {
    const float* x  = (const float*)d_in[0];
    const int*   ei = (const int*)d_in[1];
    const float* W1 = (const float*)d_in[2];
    const float* b1 = (const float*)d_in[3];
    const float* W2 = (const float*)d_in[4];
    const float* b2 = (const float*)d_in[5];
    const float* W3 = (const float*)d_in[6];
    const float* b3 = (const float*)d_in[7];
    float*       out = (float*)d_out;

    const int N = in_sizes[0] / DIM;
    const int E = in_sizes[1] / 2;
    const int* src = ei;
    const int* dst = ei + E;

    __half *h, *a;
    float* dinv;
    int *deg, *cnt, *rowptr, *bsum, *csr_src;
    uint2* tbl;
    cudaGetSymbolAddress((void**)&h,       g_h);
    cudaGetSymbolAddress((void**)&a,       g_a);
    cudaGetSymbolAddress((void**)&dinv,    g_dinv);
    cudaGetSymbolAddress((void**)&deg,     g_deg);
    cudaGetSymbolAddress((void**)&cnt,     g_cnt);
    cudaGetSymbolAddress((void**)&rowptr,  g_rowptr);
    cudaGetSymbolAddress((void**)&bsum,    g_bsum);
    cudaGetSymbolAddress((void**)&csr_src, g_csr_src);
    cudaGetSymbolAddress((void**)&tbl,     g_bfrag);

    // One-time: side stream + events (no device memory involved)
    static cudaStream_t sB = nullptr;
    static cudaEvent_t evFork = nullptr, evJoin = nullptr;
    if (!sB) {
        cudaStreamCreateWithFlags(&sB, cudaStreamNonBlocking);
        cudaEventCreateWithFlags(&evFork, cudaEventDisableTiming);
        cudaEventCreateWithFlags(&evJoin, cudaEventDisableTiming);
        cudaFuncSetAttribute(mma_gemm, cudaFuncAttributeMaxDynamicSharedMemorySize, SM_TOT);
    }

    const int TB = 256;
    const int n_blk  = (N + TB - 1) / TB;
    const int e_blk  = (E + TB - 1) / TB;
    const int gemm_g = (N + TILE_M - 1) / TILE_M;
    const int nch    = (N + 1023) / 1024;
    const int gat_blk = (int)(((long)N * 32 + TB - 1) / TB);

    // ---- fork: CSR build on side stream, prep+GEMM1 on main stream ----
    cudaEventRecord(evFork, 0);
    cudaStreamWaitEvent(sB, evFork, 0);

    // side stream: CSR chain (scan2 folded into scan3)
    zero2_kernel<<<n_blk, TB, 0, sB>>>(deg, cnt, N);
    deg_acc_kernel<<<e_blk, TB, 0, sB>>>(dst, deg, E);
    scan1_kernel<<<nch, 256, 0, sB>>>(deg, rowptr, bsum, dinv, N);
    scan3_kernel<<<n_blk, TB, 0, sB>>>(rowptr, bsum, N, E);
    fill_kernel<<<e_blk, TB, 0, sB>>>(src, dst, rowptr, cnt, csr_src, E);
    cudaEventRecord(evJoin, sB);

    // main stream: prep + layer-1 GEMM
    prep_kernel<<<8192, TB>>>(W1, W2, W3, tbl, x, a, N);
    mma_gemm<<<gemm_g, NTHR, SM_TOT>>>(a, tbl, h, N);

    // join before aggregation
    cudaStreamWaitEvent(0, evJoin, 0);

    // layer 1 aggregation -> fp16 plane
    gather_kernel<true, true><<<gat_blk, TB>>>(h, b1, rowptr, csr_src, dinv,
                                               nullptr, a, N);
    // layer 2
    mma_gemm<<<gemm_g, NTHR, SM_TOT>>>(a, tbl + TBL_PER_LAYER, h, N);
    gather_kernel<true, true><<<gat_blk, TB>>>(h, b2, rowptr, csr_src, dinv,
                                               nullptr, a, N);
    // layer 3 -> d_out (fp32)
    mma_gemm<<<gemm_g, NTHR, SM_TOT>>>(a, tbl + 2 * TBL_PER_LAYER, h, N);
    gather_kernel<false, false><<<gat_blk, TB>>>(h, b3, rowptr, csr_src, dinv,
                                                 out, nullptr, N);
}